// round 5
// baseline (speedup 1.0000x reference)
#include <cuda_runtime.h>
#include <cuda_bf16.h>
#include <cstdint>

// out[n, e] = tanh( sum_d input[n, d] * trans[urls[n], d, e] + bias[urls[n], e] )
// input [16,256,256] f32, urls [16,256] i32, trans [2000,256,256] f32, bias [2000,256] f32.
//
// v5: URL-grouped dedup + float4 loads (round 4) + UNIFORM work units:
//     prep emits one item per (url, <=4-token chunk); a unit is
//     (item, column-half) = one 128KB matrix-half stream. Persistent grid of
//     148*12 CTAs strides over units -> near-perfect load balance.
//     __launch_bounds__(128,12) raises occupancy cap to 75%.

#define D 256
#define D4 64            // D/4 float4 per row
#define N_TOKENS 4096
#define N_URLS 2000
#define CHUNK 4          // tokens per matrix pass
#define GRID_MAIN (148 * 12)

// ---- scratch ----
__device__ int g_counts[N_URLS];
__device__ int g_offsets[N_URLS];
__device__ int g_token_list[N_TOKENS];
__device__ int g_items[N_TOKENS];     // (url << 12) | cbase
__device__ int g_nunits;              // 2 * n_items

// ---- fused prep: histogram + scan + scatter + item list, one CTA ----
__global__ __launch_bounds__(1024)
void prep_kernel(const int* __restrict__ urls)
{
    __shared__ int s_cnt[N_URLS];
    __shared__ int s_off[N_URLS];
    __shared__ int s_cur[N_URLS];
    __shared__ int sbuf[2][1024];

    const int t = threadIdx.x;
    for (int i = t; i < N_URLS; i += 1024) { s_cnt[i] = 0; s_cur[i] = 0; }
    __syncthreads();
    for (int n = t; n < N_TOKENS; n += 1024) atomicAdd(&s_cnt[urls[n]], 1);
    __syncthreads();

    const int i0 = 2 * t, i1 = 2 * t + 1;
    const int c0 = (i0 < N_URLS) ? s_cnt[i0] : 0;
    const int c1 = (i1 < N_URLS) ? s_cnt[i1] : 0;

    // ---- scan 1: token offsets ----
    sbuf[0][t] = c0 + c1;
    __syncthreads();
    int src = 0;
    #pragma unroll
    for (int stride = 1; stride < 1024; stride <<= 1) {
        int v = sbuf[src][t];
        if (t >= stride) v += sbuf[src][t - stride];
        sbuf[src ^ 1][t] = v;
        src ^= 1;
        __syncthreads();
    }
    const int excl = sbuf[src][t] - (c0 + c1);
    if (i0 < N_URLS) { s_off[i0] = excl;      g_offsets[i0] = excl;      g_counts[i0] = c0; }
    if (i1 < N_URLS) { s_off[i1] = excl + c0; g_offsets[i1] = excl + c0; g_counts[i1] = c1; }
    __syncthreads();

    // scatter token ids into compacted per-url lists
    for (int n = t; n < N_TOKENS; n += 1024) {
        const int u = urls[n];
        const int pos = atomicAdd(&s_cur[u], 1);
        g_token_list[s_off[u] + pos] = n;
    }

    // ---- scan 2: item offsets (nchunk = ceil(count/4) per url) ----
    const int nch0 = (c0 + CHUNK - 1) >> 2;
    const int nch1 = (c1 + CHUNK - 1) >> 2;
    __syncthreads();
    sbuf[src][t] = nch0 + nch1;   // reuse current src buffer as level 0
    __syncthreads();
    #pragma unroll
    for (int stride = 1; stride < 1024; stride <<= 1) {
        int v = sbuf[src][t];
        if (t >= stride) v += sbuf[src][t - stride];
        sbuf[src ^ 1][t] = v;
        src ^= 1;
        __syncthreads();
    }
    const int excl2 = sbuf[src][t] - (nch0 + nch1);
    if (i0 < N_URLS)
        for (int j = 0; j < nch0; j++)
            g_items[excl2 + j] = (i0 << 12) | (j * CHUNK);
    if (i1 < N_URLS)
        for (int j = 0; j < nch1; j++)
            g_items[excl2 + nch0 + j] = (i1 << 12) | (j * CHUNK);
    if (t == 1023) g_nunits = 2 * sbuf[src][1023];
}

// ---- main compute ----
// CTA: 128 threads = 32 column-groups (cg) x 4 row-slices (rs), rs in lane
// bits [0:2) so the 4-way cross-slice reduction is two shfl_xor.
// A unit = (item, half): stream one 128KB column-half of trans[u], apply to
// <=4 tokens. Persistent CTAs stride over units for load balance.
template<int K>
__device__ __forceinline__ void accum_and_store(
    const float4* __restrict__ T4, const float* __restrict__ xs_s,
    const int* tok_s, const float4& bv, float4* __restrict__ out4,
    int cidx, int rs)
{
    float4 acc[K];
    #pragma unroll
    for (int kk = 0; kk < K; kk++) acc[kk] = make_float4(0.f, 0.f, 0.f, 0.f);

    #pragma unroll 4
    for (int d = rs; d < D; d += 4) {
        const float4 v = T4[d * D4 + cidx];
        #pragma unroll
        for (int kk = 0; kk < K; kk++) {
            const float x = xs_s[kk * D + d];
            acc[kk].x = fmaf(x, v.x, acc[kk].x);
            acc[kk].y = fmaf(x, v.y, acc[kk].y);
            acc[kk].z = fmaf(x, v.z, acc[kk].z);
            acc[kk].w = fmaf(x, v.w, acc[kk].w);
        }
    }

    #pragma unroll
    for (int kk = 0; kk < K; kk++) {
        #pragma unroll
        for (int s = 1; s <= 2; s <<= 1) {
            acc[kk].x += __shfl_xor_sync(0xffffffffu, acc[kk].x, s);
            acc[kk].y += __shfl_xor_sync(0xffffffffu, acc[kk].y, s);
            acc[kk].z += __shfl_xor_sync(0xffffffffu, acc[kk].z, s);
            acc[kk].w += __shfl_xor_sync(0xffffffffu, acc[kk].w, s);
        }
    }

    if (rs == 0) {
        #pragma unroll
        for (int kk = 0; kk < K; kk++) {
            float4 r;
            r.x = tanhf(acc[kk].x + bv.x);
            r.y = tanhf(acc[kk].y + bv.y);
            r.z = tanhf(acc[kk].z + bv.z);
            r.w = tanhf(acc[kk].w + bv.w);
            out4[(size_t)tok_s[kk] * D4 + cidx] = r;
        }
    }
}

__global__ __launch_bounds__(128, 12)
void grouped_kernel(const float4* __restrict__ inp4,
                    const float4* __restrict__ trans4,
                    const float4* __restrict__ bias4,
                    float4*       __restrict__ out4)
{
    const int tid = threadIdx.x;
    const int cg  = tid >> 2;
    const int rs  = tid & 3;

    __shared__ float xs_s[CHUNK * D];
    __shared__ int tok_s[CHUNK];

    const int nunits = g_nunits;
    bool first = true;

    for (int unit = blockIdx.x; unit < nunits; unit += GRID_MAIN) {
        const int item  = g_items[unit >> 1];
        const int half  = unit & 1;
        const int u     = item >> 12;
        const int cbase = item & 0xFFF;
        const int k     = min(CHUNK, g_counts[u] - cbase);
        const int boff  = g_offsets[u];

        if (!first) __syncthreads();   // protect smem reuse across units
        first = false;
        if (tid < k) tok_s[tid] = g_token_list[boff + cbase + tid];
        __syncthreads();
        for (int idx = tid; idx < k * D4; idx += 128) {
            const int kk = idx >> 6;
            const int c  = idx & 63;
            reinterpret_cast<float4*>(xs_s)[kk * D4 + c] =
                inp4[(size_t)tok_s[kk] * D4 + c];
        }
        __syncthreads();

        const int cidx = half * 32 + cg;
        const float4 bv = bias4[(size_t)u * D4 + cidx];
        const float4* __restrict__ T4 = trans4 + (size_t)u * D * D4;

        switch (k) {
            case 1: accum_and_store<1>(T4, xs_s, tok_s, bv, out4, cidx, rs); break;
            case 2: accum_and_store<2>(T4, xs_s, tok_s, bv, out4, cidx, rs); break;
            case 3: accum_and_store<3>(T4, xs_s, tok_s, bv, out4, cidx, rs); break;
            default: accum_and_store<4>(T4, xs_s, tok_s, bv, out4, cidx, rs); break;
        }
    }
}

extern "C" void kernel_launch(void* const* d_in, const int* in_sizes, int n_in,
                              void* d_out, int out_size)
{
    const float4* inp4   = (const float4*)d_in[0];
    const int*    urls   = (const int*)   d_in[1];
    const float4* trans4 = (const float4*)d_in[2];
    const float4* bias4  = (const float4*)d_in[3];
    float4*       out4   = (float4*)      d_out;

    prep_kernel<<<1, 1024>>>(urls);
    grouped_kernel<<<GRID_MAIN, 128>>>(inp4, trans4, bias4, out4);
}

// round 6
// speedup vs baseline: 1.4623x; 1.4623x over previous
#include <cuda_runtime.h>
#include <cuda_bf16.h>
#include <cstdint>

// out[n, e] = tanh( sum_d input[n, d] * trans[urls[n], d, e] + bias[urls[n], e] )
// input [16,256,256] f32, urls [16,256] i32, trans [2000,256,256] f32, bias [2000,256] f32.
//
// v6: URL-grouped dedup (474MB traffic) + cp.async.bulk (TMA) double-buffered
//     pipeline so DRAM saturation no longer depends on warp-level MLP.
//     One unit = (url, <=4-token chunk) = one full 256KB matrix stream,
//     16 stages x 16KB, 2 smem buffers, mbarrier expect_tx completion.
//     Persistent grid 148*6 CTAs (smem-limited 6/SM), 128 threads each.

#define D 256
#define N_TOKENS 4096
#define N_URLS 2000
#define CHUNK 4
#define ROWS_PER_STAGE 16
#define STAGE_FLOATS (ROWS_PER_STAGE * D)        // 4096 floats = 16KB
#define STAGE_BYTES  (STAGE_FLOATS * 4)
#define N_STAGES     (D / ROWS_PER_STAGE)        // 16
#define GRID_MAIN    (148 * 6)

// ---- scratch ----
__device__ int g_counts[N_URLS];
__device__ int g_offsets[N_URLS];
__device__ int g_token_list[N_TOKENS];
__device__ int g_items[N_TOKENS];     // (url << 12) | cbase
__device__ int g_nitems;

// ---- PTX helpers ----
__device__ __forceinline__ uint32_t smem_u32(const void* p) {
    return (uint32_t)__cvta_generic_to_shared(p);
}
__device__ __forceinline__ void mbar_init(uint32_t addr, uint32_t count) {
    asm volatile("mbarrier.init.shared.b64 [%0], %1;" :: "r"(addr), "r"(count) : "memory");
}
__device__ __forceinline__ void mbar_expect_tx(uint32_t addr, uint32_t bytes) {
    asm volatile("mbarrier.arrive.expect_tx.shared.b64 _, [%0], %1;"
                 :: "r"(addr), "r"(bytes) : "memory");
}
__device__ __forceinline__ void bulk_g2s(uint32_t dst, const void* src,
                                         uint32_t bytes, uint32_t mbar) {
    asm volatile("cp.async.bulk.shared::cta.global.mbarrier::complete_tx::bytes "
                 "[%0], [%1], %2, [%3];"
                 :: "r"(dst), "l"(src), "r"(bytes), "r"(mbar) : "memory");
}
__device__ __forceinline__ void mbar_wait(uint32_t addr, uint32_t parity) {
    asm volatile(
        "{\n\t"
        ".reg .pred P1;\n\t"
        "WAIT_LOOP_%=:\n\t"
        "mbarrier.try_wait.parity.acquire.cta.shared::cta.b64 P1, [%0], %1, 0x989680;\n\t"
        "@P1 bra.uni WAIT_DONE_%=;\n\t"
        "bra.uni WAIT_LOOP_%=;\n\t"
        "WAIT_DONE_%=:\n\t"
        "}"
        :: "r"(addr), "r"(parity) : "memory");
}

// ---- fused prep: histogram + scans + scatter + item list, one CTA ----
__global__ __launch_bounds__(1024)
void prep_kernel(const int* __restrict__ urls)
{
    __shared__ int s_cnt[N_URLS];
    __shared__ int s_off[N_URLS];
    __shared__ int s_cur[N_URLS];
    __shared__ int sbuf[2][1024];

    const int t = threadIdx.x;
    for (int i = t; i < N_URLS; i += 1024) { s_cnt[i] = 0; s_cur[i] = 0; }
    __syncthreads();
    for (int n = t; n < N_TOKENS; n += 1024) atomicAdd(&s_cnt[urls[n]], 1);
    __syncthreads();

    const int i0 = 2 * t, i1 = 2 * t + 1;
    const int c0 = (i0 < N_URLS) ? s_cnt[i0] : 0;
    const int c1 = (i1 < N_URLS) ? s_cnt[i1] : 0;

    // scan 1: token offsets
    sbuf[0][t] = c0 + c1;
    __syncthreads();
    int src = 0;
    #pragma unroll
    for (int stride = 1; stride < 1024; stride <<= 1) {
        int v = sbuf[src][t];
        if (t >= stride) v += sbuf[src][t - stride];
        sbuf[src ^ 1][t] = v;
        src ^= 1;
        __syncthreads();
    }
    const int excl = sbuf[src][t] - (c0 + c1);
    if (i0 < N_URLS) { s_off[i0] = excl;      g_offsets[i0] = excl;      g_counts[i0] = c0; }
    if (i1 < N_URLS) { s_off[i1] = excl + c0; g_offsets[i1] = excl + c0; g_counts[i1] = c1; }
    __syncthreads();

    for (int n = t; n < N_TOKENS; n += 1024) {
        const int u = urls[n];
        const int pos = atomicAdd(&s_cur[u], 1);
        g_token_list[s_off[u] + pos] = n;
    }

    // scan 2: item offsets (ceil(count/4) chunks per url)
    const int nch0 = (c0 + CHUNK - 1) >> 2;
    const int nch1 = (c1 + CHUNK - 1) >> 2;
    __syncthreads();
    sbuf[src][t] = nch0 + nch1;
    __syncthreads();
    #pragma unroll
    for (int stride = 1; stride < 1024; stride <<= 1) {
        int v = sbuf[src][t];
        if (t >= stride) v += sbuf[src][t - stride];
        sbuf[src ^ 1][t] = v;
        src ^= 1;
        __syncthreads();
    }
    const int excl2 = sbuf[src][t] - (nch0 + nch1);
    if (i0 < N_URLS)
        for (int j = 0; j < nch0; j++) g_items[excl2 + j] = (i0 << 12) | (j * CHUNK);
    if (i1 < N_URLS)
        for (int j = 0; j < nch1; j++) g_items[excl2 + nch0 + j] = (i1 << 12) | (j * CHUNK);
    if (t == 1023) g_nitems = sbuf[src][1023];
}

// ---- main: persistent CTAs, bulk-async double-buffered matrix stream ----
// 128 threads/CTA. Thread t owns output columns e0=t and e1=t+128.
// xs packed transposed: xs4[d] = {x_tok0[d], x_tok1[d], x_tok2[d], x_tok3[d]}
// (one LDS.128 broadcast serves all 4 token FFMAs). Partial chunks zero-pad.
__global__ __launch_bounds__(128)
void grouped_kernel(const float* __restrict__ inp,
                    const float* __restrict__ trans,
                    const float* __restrict__ bias,
                    float*       __restrict__ out)
{
    __shared__ float  T_s[2][STAGE_FLOATS];   // 2 x 16KB
    __shared__ float4 xs4[D];                 // 4KB, [d] -> 4 token x-values
    __shared__ int    tok_s[CHUNK];
    __shared__ __align__(8) unsigned long long mbar[2];

    const int tid = threadIdx.x;
    const uint32_t mb0 = smem_u32(&mbar[0]);
    const uint32_t mb1 = smem_u32(&mbar[1]);
    const uint32_t tb0 = smem_u32(&T_s[0][0]);
    const uint32_t tb1 = smem_u32(&T_s[1][0]);

    if (tid == 0) { mbar_init(mb0, 1); mbar_init(mb1, 1); }
    __syncthreads();

    uint32_t ph0 = 0, ph1 = 0;   // per-buffer phase parity
    const int nitems = g_nitems;

    for (int unit = blockIdx.x; unit < nitems; unit += GRID_MAIN) {
        const int item  = g_items[unit];
        const int u     = item >> 12;
        const int cbase = item & 0xFFF;
        const int k     = min(CHUNK, g_counts[u] - cbase);
        const int boff  = g_offsets[u];

        __syncthreads();   // epilogue of previous unit done before smem reuse
        if (tid < CHUNK)
            tok_s[tid] = (tid < k) ? g_token_list[boff + cbase + tid] : -1;
        __syncthreads();

        // pack token vectors transposed (zero-pad beyond k)
        for (int d = tid; d < D; d += 128) {
            float4 v;
            v.x =           inp[(size_t)tok_s[0] * D + d];
            v.y = (k > 1) ? inp[(size_t)tok_s[1] * D + d] : 0.f;
            v.z = (k > 2) ? inp[(size_t)tok_s[2] * D + d] : 0.f;
            v.w = (k > 3) ? inp[(size_t)tok_s[3] * D + d] : 0.f;
            xs4[d] = v;
        }
        __syncthreads();

        const float* __restrict__ T = trans + (size_t)u * D * D;
        const float b0 = bias[(size_t)u * D + tid];
        const float b1 = bias[(size_t)u * D + tid + 128];

        // prologue: fill both stages
        if (tid == 0) {
            mbar_expect_tx(mb0, STAGE_BYTES);
            bulk_g2s(tb0, T, STAGE_BYTES, mb0);
            mbar_expect_tx(mb1, STAGE_BYTES);
            bulk_g2s(tb1, T + STAGE_FLOATS, STAGE_BYTES, mb1);
        }

        float4 acc0 = make_float4(0.f, 0.f, 0.f, 0.f);  // col e0, tokens 0..3
        float4 acc1 = make_float4(0.f, 0.f, 0.f, 0.f);  // col e1

        for (int s = 0; s < N_STAGES; s++) {
            const int bsel = s & 1;
            if (bsel == 0) { mbar_wait(mb0, ph0); ph0 ^= 1; }
            else           { mbar_wait(mb1, ph1); ph1 ^= 1; }

            const float* buf = T_s[bsel];
            const int dbase = s * ROWS_PER_STAGE;
            #pragma unroll 4
            for (int r = 0; r < ROWS_PER_STAGE; r++) {
                const float4 x = xs4[dbase + r];
                const float t0 = buf[r * D + tid];
                const float t1 = buf[r * D + tid + 128];
                acc0.x = fmaf(x.x, t0, acc0.x);
                acc0.y = fmaf(x.y, t0, acc0.y);
                acc0.z = fmaf(x.z, t0, acc0.z);
                acc0.w = fmaf(x.w, t0, acc0.w);
                acc1.x = fmaf(x.x, t1, acc1.x);
                acc1.y = fmaf(x.y, t1, acc1.y);
                acc1.z = fmaf(x.z, t1, acc1.z);
                acc1.w = fmaf(x.w, t1, acc1.w);
            }
            __syncthreads();   // all consumers done with this buffer
            if (tid == 0 && s + 2 < N_STAGES) {
                const uint32_t mb = bsel ? mb1 : mb0;
                const uint32_t tb = bsel ? tb1 : tb0;
                mbar_expect_tx(mb, STAGE_BYTES);
                bulk_g2s(tb, T + (size_t)(s + 2) * STAGE_FLOATS, STAGE_BYTES, mb);
            }
        }

        // epilogue
        {
            const float* a0 = (const float*)&acc0;
            const float* a1 = (const float*)&acc1;
            #pragma unroll
            for (int kk = 0; kk < CHUNK; kk++) {
                if (kk < k) {
                    const size_t nb = (size_t)tok_s[kk] * D;
                    out[nb + tid]       = tanhf(a0[kk] + b0);
                    out[nb + tid + 128] = tanhf(a1[kk] + b1);
                }
            }
        }
    }
}

extern "C" void kernel_launch(void* const* d_in, const int* in_sizes, int n_in,
                              void* d_out, int out_size)
{
    const float* inp   = (const float*)d_in[0];
    const int*   urls  = (const int*)  d_in[1];
    const float* trans = (const float*)d_in[2];
    const float* bias  = (const float*)d_in[3];
    float*       out   = (float*)      d_out;

    prep_kernel<<<1, 1024>>>(urls);
    grouped_kernel<<<GRID_MAIN, 128>>>(inp, trans, bias, out);
}